// round 3
// baseline (speedup 1.0000x reference)
#include <cuda_runtime.h>
#include <cuda_bf16.h>
#include <cstdint>

#define B_SZ   1024
#define K_SZ   512
#define D_SZ   256
#define H_SZ   8
#define HD_SZ  32
#define EPS_LN 1e-5f
#define Q_SCALE 0.17677669529663687f   // 32^-0.5

// ---------------- scratch (device globals; allocation-free) ----------------
__device__ float g_q[B_SZ * D_SZ];                     // 1 MB  (LN'd, scaled q)
__device__ float g_k[(size_t)B_SZ * K_SZ * D_SZ];      // 512 MB (LN'd k-proj)
__device__ float g_v[(size_t)B_SZ * K_SZ * D_SZ];      // 512 MB (v-proj)

// ============================================================================
// Kernel 1: q = LN_perhead(x_q @ Wq^T) * scale          grid=B, block=256
// warp == head (hd == 32), lane holds one channel -> pure shuffle LN
// ============================================================================
__global__ void qproj_kernel(const float* __restrict__ xq,
                             const float* __restrict__ Wq,
                             const float* __restrict__ qn_w,
                             const float* __restrict__ qn_b)
{
    const int b = blockIdx.x;
    const int j = threadIdx.x;          // output column 0..255
    const int lane = j & 31;

    __shared__ float xrow[D_SZ];
    xrow[j] = xq[b * D_SZ + j];
    __syncthreads();

    const float4* w4 = reinterpret_cast<const float4*>(Wq + (size_t)j * D_SZ);
    const float4* x4 = reinterpret_cast<const float4*>(xrow);
    float acc = 0.f;
#pragma unroll
    for (int d = 0; d < D_SZ / 4; ++d) {
        float4 w = w4[d];
        float4 x = x4[d];
        acc = fmaf(w.x, x.x, acc);
        acc = fmaf(w.y, x.y, acc);
        acc = fmaf(w.z, x.z, acc);
        acc = fmaf(w.w, x.w, acc);
    }

    // per-head LN across the warp (32 values)
    float s = acc, ss = acc * acc;
#pragma unroll
    for (int o = 16; o > 0; o >>= 1) {
        s  += __shfl_xor_sync(0xffffffffu, s,  o);
        ss += __shfl_xor_sync(0xffffffffu, ss, o);
    }
    const float mu  = s * (1.f / 32.f);
    const float var = ss * (1.f / 32.f) - mu * mu;
    const float r   = rsqrtf(var + EPS_LN);
    float q = (acc - mu) * r * qn_w[lane] + qn_b[lane];
    g_q[b * D_SZ + j] = q * Q_SCALE;
}

// ============================================================================
// Kernel 2: Out[M,256] = X[M,256] @ W^T[256,256], optional fused per-head LN.
//   M = B*K = 524288, BM=64, BN=256 (full row), BK=16, 256 thr, 8x8 micro-tile
//   thread (ty=tid/32, tx=tid%32): rows ty*8..+7, cols tx*8..+7
//   head of thread's cols = tx/4 (4 adjacent lanes own one head) -> LN via
//   2 intra-warp shuffles, no extra memory traffic.
// ============================================================================
#define BM 64
#define BK 16

template<bool DO_LN>
__global__ void __launch_bounds__(256, 2)
proj_kernel(const float* __restrict__ X,
            const float* __restrict__ W,
            const float* __restrict__ ln_w,
            const float* __restrict__ ln_b)
{
    __shared__ float sX[BK][BM];     // [d][m]   4 KB
    __shared__ float sW[BK][D_SZ];   // [d][n]  16 KB

    float* __restrict__ Out = DO_LN ? g_k : g_v;

    const int tid = threadIdx.x;
    const int tx  = tid & 31;
    const int ty  = tid >> 5;
    const size_t m_base = (size_t)blockIdx.x * BM;

    float acc[8][8];
#pragma unroll
    for (int i = 0; i < 8; ++i)
#pragma unroll
        for (int j = 0; j < 8; ++j) acc[i][j] = 0.f;

    // X tile load mapping: thread -> (row lm, 4 consecutive d at ld4)
    const int lm  = tid >> 2;        // 0..63
    const int ld4 = (tid & 3) * 4;   // 0,4,8,12
    const float* xptr = X + (m_base + lm) * D_SZ + ld4;
    const float* wptr = W + (size_t)tid * D_SZ;   // thread loads W[tid][kk..kk+15]

    for (int kk = 0; kk < D_SZ; kk += BK) {
        float4 xv = *reinterpret_cast<const float4*>(xptr + kk);
        const float4* wp = reinterpret_cast<const float4*>(wptr + kk);
        float4 w0 = wp[0], w1 = wp[1], w2 = wp[2], w3 = wp[3];

        sX[ld4 + 0][lm] = xv.x;
        sX[ld4 + 1][lm] = xv.y;
        sX[ld4 + 2][lm] = xv.z;
        sX[ld4 + 3][lm] = xv.w;

        sW[ 0][tid] = w0.x; sW[ 1][tid] = w0.y; sW[ 2][tid] = w0.z; sW[ 3][tid] = w0.w;
        sW[ 4][tid] = w1.x; sW[ 5][tid] = w1.y; sW[ 6][tid] = w1.z; sW[ 7][tid] = w1.w;
        sW[ 8][tid] = w2.x; sW[ 9][tid] = w2.y; sW[10][tid] = w2.z; sW[11][tid] = w2.w;
        sW[12][tid] = w3.x; sW[13][tid] = w3.y; sW[14][tid] = w3.z; sW[15][tid] = w3.w;
        __syncthreads();

#pragma unroll
        for (int d = 0; d < BK; ++d) {
            float4 a0 = *reinterpret_cast<const float4*>(&sX[d][ty * 8]);
            float4 a1 = *reinterpret_cast<const float4*>(&sX[d][ty * 8 + 4]);
            float4 b0 = *reinterpret_cast<const float4*>(&sW[d][tx * 8]);
            float4 b1 = *reinterpret_cast<const float4*>(&sW[d][tx * 8 + 4]);
            float a[8]  = {a0.x, a0.y, a0.z, a0.w, a1.x, a1.y, a1.z, a1.w};
            float bb[8] = {b0.x, b0.y, b0.z, b0.w, b1.x, b1.y, b1.z, b1.w};
#pragma unroll
            for (int i = 0; i < 8; ++i)
#pragma unroll
                for (int j = 0; j < 8; ++j)
                    acc[i][j] = fmaf(a[i], bb[j], acc[i][j]);
        }
        __syncthreads();
    }

    // ---- epilogue ----
    float lw[8], lb[8];
    if (DO_LN) {
        const int c0 = (tx & 3) * 8;   // channel-in-head base for this thread's cols
#pragma unroll
        for (int j = 0; j < 8; ++j) { lw[j] = ln_w[c0 + j]; lb[j] = ln_b[c0 + j]; }
    }

#pragma unroll
    for (int rr = 0; rr < 8; ++rr) {
        if (DO_LN) {
            float s = 0.f, ss = 0.f;
#pragma unroll
            for (int j = 0; j < 8; ++j) {
                s  += acc[rr][j];
                ss += acc[rr][j] * acc[rr][j];
            }
            // reduce across the 4 lanes holding this (row, head); groups are
            // 4-aligned so xor 1,2 stay in-group.
            s  += __shfl_xor_sync(0xffffffffu, s,  1);
            ss += __shfl_xor_sync(0xffffffffu, ss, 1);
            s  += __shfl_xor_sync(0xffffffffu, s,  2);
            ss += __shfl_xor_sync(0xffffffffu, ss, 2);
            const float mu  = s * (1.f / 32.f);
            const float var = ss * (1.f / 32.f) - mu * mu;
            const float r   = rsqrtf(var + EPS_LN);
#pragma unroll
            for (int j = 0; j < 8; ++j)
                acc[rr][j] = (acc[rr][j] - mu) * r * lw[j] + lb[j];
        }
        float* orow = Out + (m_base + (size_t)(ty * 8 + rr)) * D_SZ + tx * 8;
        *reinterpret_cast<float4*>(orow)     = make_float4(acc[rr][0], acc[rr][1], acc[rr][2], acc[rr][3]);
        *reinterpret_cast<float4*>(orow + 4) = make_float4(acc[rr][4], acc[rr][5], acc[rr][6], acc[rr][7]);
    }
}

// ============================================================================
// Kernel 3: flash (online-softmax) single-query attention + output LN + Wp
//   grid=B, block=256; warp == head; lane == channel-in-head.
// ============================================================================
__global__ void attn_kernel(const float* __restrict__ Wp,
                            const float* __restrict__ n_w,
                            const float* __restrict__ n_b,
                            float* __restrict__ out)
{
    const int b    = blockIdx.x;
    const int tid  = threadIdx.x;
    const int h    = tid >> 5;
    const int lane = tid & 31;

    const float q = g_q[b * D_SZ + h * HD_SZ + lane];
    const float* kp = g_k + (size_t)b * K_SZ * D_SZ + h * HD_SZ + lane;
    const float* vp = g_v + (size_t)b * K_SZ * D_SZ + h * HD_SZ + lane;

    float m = -1e30f, l = 0.f, acc = 0.f;

    for (int k0 = 0; k0 < K_SZ; k0 += 4) {
        float kv[4], vv[4];
#pragma unroll
        for (int u = 0; u < 4; ++u) {
            kv[u] = kp[(size_t)(k0 + u) * D_SZ];
            vv[u] = vp[(size_t)(k0 + u) * D_SZ];
        }
        float s[4];
#pragma unroll
        for (int u = 0; u < 4; ++u) s[u] = q * kv[u];
#pragma unroll
        for (int o = 16; o > 0; o >>= 1) {
#pragma unroll
            for (int u = 0; u < 4; ++u)
                s[u] += __shfl_xor_sync(0xffffffffu, s[u], o);
        }
#pragma unroll
        for (int u = 0; u < 4; ++u) {
            const float mn   = fmaxf(m, s[u]);
            const float corr = __expf(m - mn);
            const float p    = __expf(s[u] - mn);
            l   = l * corr + p;
            acc = acc * corr + p * vv[u];
            m   = mn;
        }
    }
    const float o_val = acc / l;

    // ---- block LN over 256 channels ----
    __shared__ float sred[2][8];
    float s = o_val, ss = o_val * o_val;
#pragma unroll
    for (int o = 16; o > 0; o >>= 1) {
        s  += __shfl_xor_sync(0xffffffffu, s,  o);
        ss += __shfl_xor_sync(0xffffffffu, ss, o);
    }
    if (lane == 0) { sred[0][h] = s; sred[1][h] = ss; }
    __syncthreads();
    float ts = 0.f, tss = 0.f;
#pragma unroll
    for (int i = 0; i < 8; ++i) { ts += sred[0][i]; tss += sred[1][i]; }
    const float mu  = ts * (1.f / 256.f);
    const float var = tss * (1.f / 256.f) - mu * mu;
    const float r   = rsqrtf(var + EPS_LN);

    __shared__ float sn[D_SZ];
    sn[tid] = (o_val - mu) * r * n_w[tid] + n_b[tid];
    __syncthreads();

    // ---- out @ Wp^T : thread tid = output column ----
    const float4* w4 = reinterpret_cast<const float4*>(Wp + (size_t)tid * D_SZ);
    const float4* x4 = reinterpret_cast<const float4*>(sn);
    float a = 0.f;
#pragma unroll
    for (int d = 0; d < D_SZ / 4; ++d) {
        float4 w = w4[d];
        float4 x = x4[d];
        a = fmaf(w.x, x.x, a);
        a = fmaf(w.y, x.y, a);
        a = fmaf(w.z, x.z, a);
        a = fmaf(w.w, x.w, a);
    }
    out[b * D_SZ + tid] = a;
}

// ============================================================================
extern "C" void kernel_launch(void* const* d_in, const int* in_sizes, int n_in,
                              void* d_out, int out_size)
{
    const float* x_q  = (const float*)d_in[0];
    const float* x_k  = (const float*)d_in[1];
    const float* x_v  = (const float*)d_in[2];
    const float* Wq   = (const float*)d_in[3];
    const float* Wk   = (const float*)d_in[4];
    const float* Wv   = (const float*)d_in[5];
    const float* Wp   = (const float*)d_in[6];
    const float* qn_w = (const float*)d_in[7];
    const float* qn_b = (const float*)d_in[8];
    const float* kn_w = (const float*)d_in[9];
    const float* kn_b = (const float*)d_in[10];
    const float* n_w  = (const float*)d_in[11];
    const float* n_b  = (const float*)d_in[12];
    float* out = (float*)d_out;

    const int M_BLOCKS = (B_SZ * K_SZ) / BM;   // 8192

    qproj_kernel<<<B_SZ, 256>>>(x_q, Wq, qn_w, qn_b);
    proj_kernel<true ><<<M_BLOCKS, 256>>>(x_k, Wk, kn_w, kn_b);
    proj_kernel<false><<<M_BLOCKS, 256>>>(x_v, Wv, nullptr, nullptr);
    attn_kernel<<<B_SZ, 256>>>(Wp, n_w, n_b, out);
}

// round 6
// speedup vs baseline: 3.8496x; 3.8496x over previous
#include <cuda_runtime.h>
#include <cuda_bf16.h>
#include <cstdint>

#define B_SZ   1024
#define K_SZ   512
#define D_SZ   256
#define H_SZ   8
#define HD_SZ  32
#define EPS_LN 1e-5f
#define Q_SCALE 0.17677669529663687f   // 32^-0.5

// ---------------- scratch (device globals; allocation-free) ----------------
__device__ float g_q[B_SZ * D_SZ];                        // 1 MB
__device__ float g_k[(size_t)B_SZ * K_SZ * D_SZ];         // 512 MB
__device__ float g_v[(size_t)B_SZ * K_SZ * D_SZ];         // 512 MB
__device__ __nv_bfloat16 g_wh[2][D_SZ * D_SZ];            // W hi (0=Wk,1=Wv)
__device__ __nv_bfloat16 g_wl[2][D_SZ * D_SZ];            // W lo

// ======================= helpers ==============================
__device__ __forceinline__ uint32_t smem_u32(const void* p) {
    uint32_t a;
    asm("{ .reg .u64 t; cvta.to.shared.u64 t, %1; cvt.u32.u64 %0, t; }"
        : "=r"(a) : "l"(p));
    return a;
}
__device__ __forceinline__ uint32_t pack_bf2(float a, float b) {
    __nv_bfloat162 t = __floats2bfloat162_rn(a, b);
    return *reinterpret_cast<uint32_t*>(&t);
}

#define LDSM4(r0, r1, r2, r3, addr) \
    asm volatile("ldmatrix.sync.aligned.m8n8.x4.shared.b16 {%0,%1,%2,%3}, [%4];" \
                 : "=r"(r0), "=r"(r1), "=r"(r2), "=r"(r3) : "r"(addr))

#define MMA16816(c, a, b) \
    asm volatile("mma.sync.aligned.m16n8k16.row.col.f32.bf16.bf16.f32 " \
                 "{%0,%1,%2,%3}, {%4,%5,%6,%7}, {%8,%9}, {%0,%1,%2,%3};" \
                 : "+f"((c)[0]), "+f"((c)[1]), "+f"((c)[2]), "+f"((c)[3]) \
                 : "r"((a)[0]), "r"((a)[1]), "r"((a)[2]), "r"((a)[3]), \
                   "r"((b)[0]), "r"((b)[1]))

#define CP16(dst, gsrc) \
    asm volatile("cp.async.ca.shared.global [%0], [%1], 16;" \
                 :: "r"(dst), "l"(gsrc) : "memory")
#define CP_COMMIT() asm volatile("cp.async.commit_group;" ::: "memory")
#define CP_WAIT0()  asm volatile("cp.async.wait_group 0;" ::: "memory")

// ============================================================================
// Kernel 0: split Wk/Wv into bf16 hi/lo.  grid=512, block=256
// ============================================================================
__global__ void wsplit_kernel(const float* __restrict__ Wk,
                              const float* __restrict__ Wv)
{
    const int sel = blockIdx.x & 1;
    const int i   = (blockIdx.x >> 1) * 256 + threadIdx.x;
    const float w = (sel ? Wv : Wk)[i];
    const __nv_bfloat16 hi = __float2bfloat16(w);
    g_wh[sel][i] = hi;
    g_wl[sel][i] = __float2bfloat16(w - __bfloat162float(hi));
}

// ============================================================================
// Kernel 1: q = LN_perhead(x_q @ Wq^T) * scale          grid=B, block=256
// ============================================================================
__global__ void qproj_kernel(const float* __restrict__ xq,
                             const float* __restrict__ Wq,
                             const float* __restrict__ qn_w,
                             const float* __restrict__ qn_b)
{
    const int b = blockIdx.x;
    const int j = threadIdx.x;
    const int lane = j & 31;

    __shared__ float xrow[D_SZ];
    xrow[j] = xq[b * D_SZ + j];
    __syncthreads();

    const float4* w4 = reinterpret_cast<const float4*>(Wq + (size_t)j * D_SZ);
    const float4* x4 = reinterpret_cast<const float4*>(xrow);
    float acc = 0.f;
#pragma unroll
    for (int d = 0; d < D_SZ / 4; ++d) {
        float4 w = w4[d];
        float4 x = x4[d];
        acc = fmaf(w.x, x.x, acc);
        acc = fmaf(w.y, x.y, acc);
        acc = fmaf(w.z, x.z, acc);
        acc = fmaf(w.w, x.w, acc);
    }
    float s = acc, ss = acc * acc;
#pragma unroll
    for (int o = 16; o > 0; o >>= 1) {
        s  += __shfl_xor_sync(0xffffffffu, s,  o);
        ss += __shfl_xor_sync(0xffffffffu, ss, o);
    }
    const float mu  = s * (1.f / 32.f);
    const float var = ss * (1.f / 32.f) - mu * mu;
    const float r   = rsqrtf(var + EPS_LN);
    float q = (acc - mu) * r * qn_w[lane] + qn_b[lane];
    g_q[b * D_SZ + j] = q * Q_SCALE;
}

// ============================================================================
// Kernel 2 (mma.sync bf16 hi/lo): Out[M,256] = X[M,256] @ W^T
//   CTA: M=64, N=256, K chunks of 64, double-buffered smem, SW128 swizzle.
//   8 warps; warp w owns N cols [32w, 32w+32) == head w. 3 MMA passes.
// ============================================================================
#define CH       64
#define NCH      (D_SZ / CH)      // 4
#define OFF_AH   0                 // 64 rows * 128B = 8 KB
#define OFF_AL   8192
#define OFF_WH   16384             // 256 rows * 128B = 32 KB
#define OFF_WL   49152
#define STAGE_B  81920             // 80 KB per stage
#define DSM_B    (2 * STAGE_B + 1024)

template<bool DO_LN>
__global__ void __launch_bounds__(256, 1)
proj_mma(const float* __restrict__ X, int wsel,
         const float* __restrict__ lnw, const float* __restrict__ lnb)
{
    extern __shared__ char dsm[];
    char* smp = (char*)((((uintptr_t)dsm) + 1023) & ~(uintptr_t)1023);
    const uint32_t base = smem_u32(smp);

    const int tid  = threadIdx.x;
    const int wid  = tid >> 5;
    const int lane = tid & 31;
    const size_t m_base = (size_t)blockIdx.x * 64;

    const __nv_bfloat16* __restrict__ Wh = g_wh[wsel];
    const __nv_bfloat16* __restrict__ Wl = g_wl[wsel];

    // LN gamma/beta per thread-column (head == warp's 32 cols)
    float lw[4][2], lb[4][2];
    if (DO_LN) {
#pragma unroll
        for (int j = 0; j < 4; ++j) {
            const int c = 8 * j + 2 * (lane & 3);
            lw[j][0] = lnw[c];     lw[j][1] = lnw[c + 1];
            lb[j][0] = lnb[c];     lb[j][1] = lnb[c + 1];
        }
    }

    // ---- X load/convert mapping: thread -> row tid>>2, 16 floats ----
    const int xrow  = tid >> 2;
    const int xcol  = (tid & 3) * 16;          // float index in 64-wide chunk
    const float* xptr = X + (m_base + xrow) * D_SZ + xcol;
    const uint32_t xxor = (uint32_t)(xrow & 7) * 16u;

    // ---- W cp.async mapping: 8 x 16B per thread per buffer ----
    // idx = tid + 256*i : row = idx>>3 (0..255), j16 = idx&7

    float acc[4][4][4];
#pragma unroll
    for (int i = 0; i < 4; ++i)
#pragma unroll
        for (int j = 0; j < 4; ++j)
#pragma unroll
            for (int cc = 0; cc < 4; ++cc) acc[i][j][cc] = 0.f;

    float4 xr[4];

    // ================= prologue: stage 0 = chunk 0 =================
    {
        const uint32_t wb = base;   // stage 0
#pragma unroll
        for (int i = 0; i < 8; ++i) {
            const int idx = tid + i * 256;
            const int row = idx >> 3;
            const int j16 = idx & 7;
            const uint32_t off = (uint32_t)row * 128u +
                                 (((uint32_t)j16 * 16u) ^ ((uint32_t)(row & 7) * 16u));
            CP16(wb + OFF_WH + off, (const char*)Wh + (size_t)row * 512 + j16 * 16);
            CP16(wb + OFF_WL + off, (const char*)Wl + (size_t)row * 512 + j16 * 16);
        }
        CP_COMMIT();
#pragma unroll
        for (int q = 0; q < 4; ++q)
            xr[q] = *reinterpret_cast<const float4*>(xptr + q * 4);
#pragma unroll
        for (int q = 0; q < 4; ++q) {
            float4 v = xr[q];
            uint2 hv, lv;
            hv.x = pack_bf2(v.x, v.y);
            hv.y = pack_bf2(v.z, v.w);
            lv.x = pack_bf2(v.x - __bfloat162float(__float2bfloat16(v.x)),
                            v.y - __bfloat162float(__float2bfloat16(v.y)));
            lv.y = pack_bf2(v.z - __bfloat162float(__float2bfloat16(v.z)),
                            v.w - __bfloat162float(__float2bfloat16(v.w)));
            const uint32_t colb = (uint32_t)(tid & 3) * 32u + (uint32_t)q * 8u;
            const uint32_t off  = (uint32_t)xrow * 128u + (colb ^ xxor);
            *reinterpret_cast<uint2*>(smp + OFF_AH + off) = hv;
            *reinterpret_cast<uint2*>(smp + OFF_AL + off) = lv;
        }
        CP_WAIT0();
        __syncthreads();
    }

    // ================= main loop over K chunks =================
    for (int c = 0; c < NCH; ++c) {
        const int s = c & 1;
        const uint32_t sb = base + s * STAGE_B;

        if (c + 1 < NCH) {
            const int kn = (c + 1) * CH;
            const uint32_t wb = base + (s ^ 1) * STAGE_B;
#pragma unroll
            for (int i = 0; i < 8; ++i) {
                const int idx = tid + i * 256;
                const int row = idx >> 3;
                const int j16 = idx & 7;
                const uint32_t off = (uint32_t)row * 128u +
                                     (((uint32_t)j16 * 16u) ^ ((uint32_t)(row & 7) * 16u));
                CP16(wb + OFF_WH + off,
                     (const char*)Wh + (size_t)row * 512 + kn * 2 + j16 * 16);
                CP16(wb + OFF_WL + off,
                     (const char*)Wl + (size_t)row * 512 + kn * 2 + j16 * 16);
            }
            CP_COMMIT();
#pragma unroll
            for (int q = 0; q < 4; ++q)
                xr[q] = *reinterpret_cast<const float4*>(xptr + kn + q * 4);
        }

        // ---------------- compute chunk c ----------------
#pragma unroll
        for (int ks = 0; ks < 4; ++ks) {
            uint32_t Ah4[4][4], Al4[4][4], Bh4[4][2], Bl4[4][2];
            {
                const int ar   = lane & 15;
                const uint32_t akhb = (uint32_t)(lane >> 4) * 16u;
#pragma unroll
                for (int i = 0; i < 4; ++i) {
                    const int row = 16 * i + ar;
                    const uint32_t off = (uint32_t)row * 128u +
                        (((uint32_t)ks * 32u + akhb) ^ ((uint32_t)(row & 7) * 16u));
                    LDSM4(Ah4[i][0], Ah4[i][1], Ah4[i][2], Ah4[i][3], sb + OFF_AH + off);
                    LDSM4(Al4[i][0], Al4[i][1], Al4[i][2], Al4[i][3], sb + OFF_AL + off);
                }
            }
            {
                const int g2  = lane >> 3;
                const uint32_t khb = (uint32_t)(g2 & 1) * 16u;
                const int rsub = ((g2 >> 1) * 8) + (lane & 7);
#pragma unroll
                for (int p = 0; p < 2; ++p) {
                    const int row = wid * 32 + p * 16 + rsub;
                    const uint32_t off = (uint32_t)row * 128u +
                        (((uint32_t)ks * 32u + khb) ^ ((uint32_t)(row & 7) * 16u));
                    LDSM4(Bh4[2 * p][0], Bh4[2 * p][1], Bh4[2 * p + 1][0], Bh4[2 * p + 1][1],
                          sb + OFF_WH + off);
                    LDSM4(Bl4[2 * p][0], Bl4[2 * p][1], Bl4[2 * p + 1][0], Bl4[2 * p + 1][1],
                          sb + OFF_WL + off);
                }
            }
#pragma unroll
            for (int i = 0; i < 4; ++i)
#pragma unroll
                for (int j = 0; j < 4; ++j) {
                    MMA16816(acc[i][j], Ah4[i], Bh4[j]);
                    MMA16816(acc[i][j], Al4[i], Bh4[j]);
                    MMA16816(acc[i][j], Ah4[i], Bl4[j]);
                }
        }

        // ---------------- stage X for chunk c+1 ----------------
        if (c + 1 < NCH) {
            char* ab = smp + (s ^ 1) * STAGE_B;
#pragma unroll
            for (int q = 0; q < 4; ++q) {
                float4 v = xr[q];
                uint2 hv, lv;
                hv.x = pack_bf2(v.x, v.y);
                hv.y = pack_bf2(v.z, v.w);
                lv.x = pack_bf2(v.x - __bfloat162float(__float2bfloat16(v.x)),
                                v.y - __bfloat162float(__float2bfloat16(v.y)));
                lv.y = pack_bf2(v.z - __bfloat162float(__float2bfloat16(v.z)),
                                v.w - __bfloat162float(__float2bfloat16(v.w)));
                const uint32_t colb = (uint32_t)(tid & 3) * 32u + (uint32_t)q * 8u;
                const uint32_t off  = (uint32_t)xrow * 128u + (colb ^ xxor);
                *reinterpret_cast<uint2*>(ab + OFF_AH + off) = hv;
                *reinterpret_cast<uint2*>(ab + OFF_AL + off) = lv;
            }
            CP_WAIT0();
        }
        __syncthreads();
    }

    // ================= epilogue: per-head LN + store =================
    float* __restrict__ Out = DO_LN ? g_k : g_v;
    const int g  = lane >> 2;
    const int tg = lane & 3;
    const int ncol = wid * 32 + 2 * tg;

#pragma unroll
    for (int i = 0; i < 4; ++i) {
        // ---- row lo: regs [0],[1] ----
        {
            const int r = 16 * i + g;
            float v0[4], v1[4];
#pragma unroll
            for (int j = 0; j < 4; ++j) { v0[j] = acc[i][j][0]; v1[j] = acc[i][j][1]; }
            if (DO_LN) {
                float s = 0.f, ss = 0.f;
#pragma unroll
                for (int j = 0; j < 4; ++j) {
                    s  += v0[j] + v1[j];
                    ss += v0[j] * v0[j] + v1[j] * v1[j];
                }
                s  += __shfl_xor_sync(0xffffffffu, s,  1);
                ss += __shfl_xor_sync(0xffffffffu, ss, 1);
                s  += __shfl_xor_sync(0xffffffffu, s,  2);
                ss += __shfl_xor_sync(0xffffffffu, ss, 2);
                const float mu  = s * (1.f / 32.f);
                const float var = ss * (1.f / 32.f) - mu * mu;
                const float rr  = rsqrtf(var + EPS_LN);
#pragma unroll
                for (int j = 0; j < 4; ++j) {
                    v0[j] = (v0[j] - mu) * rr * lw[j][0] + lb[j][0];
                    v1[j] = (v1[j] - mu) * rr * lw[j][1] + lb[j][1];
                }
            }
            float* orow = Out + (m_base + r) * D_SZ + ncol;
#pragma unroll
            for (int j = 0; j < 4; ++j)
                *reinterpret_cast<float2*>(orow + 8 * j) = make_float2(v0[j], v1[j]);
        }
        // ---- row hi: regs [2],[3] ----
        {
            const int r = 16 * i + 8 + g;
            float v0[4], v1[4];
#pragma unroll
            for (int j = 0; j < 4; ++j) { v0[j] = acc[i][j][2]; v1[j] = acc[i][j][3]; }
            if (DO_LN) {
                float s = 0.f, ss = 0.f;
#pragma unroll
                for (int j = 0; j < 4; ++j) {
                    s  += v0[j] + v1[j];
                    ss += v0[j] * v0[j] + v1[j] * v1[j];
                }
                s  += __shfl_xor_sync(0xffffffffu, s,  1);
                ss += __shfl_xor_sync(0xffffffffu, ss, 1);
                s  += __shfl_xor_sync(0xffffffffu, s,  2);
                ss += __shfl_xor_sync(0xffffffffu, ss, 2);
                const float mu  = s * (1.f / 32.f);
                const float var = ss * (1.f / 32.f) - mu * mu;
                const float rr  = rsqrtf(var + EPS_LN);
#pragma unroll
                for (int j = 0; j < 4; ++j) {
                    v0[j] = (v0[j] - mu) * rr * lw[j][0] + lb[j][0];
                    v1[j] = (v1[j] - mu) * rr * lw[j][1] + lb[j][1];
                }
            }
            float* orow = Out + (m_base + r) * D_SZ + ncol;
#pragma unroll
            for (int j = 0; j < 4; ++j)
                *reinterpret_cast<float2*>(orow + 8 * j) = make_float2(v0[j], v1[j]);
        }
    }
}

// ============================================================================
// Kernel 3: flash single-query attention + output LN + Wp.  grid=B, block=256
// ============================================================================
__global__ void attn_kernel(const float* __restrict__ Wp,
                            const float* __restrict__ n_w,
                            const float* __restrict__ n_b,
                            float* __restrict__ out)
{
    const int b    = blockIdx.x;
    const int tid  = threadIdx.x;
    const int h    = tid >> 5;
    const int lane = tid & 31;

    const float q = g_q[b * D_SZ + h * HD_SZ + lane];
    const float* kp = g_k + (size_t)b * K_SZ * D_SZ + h * HD_SZ + lane;
    const float* vp = g_v + (size_t)b * K_SZ * D_SZ + h * HD_SZ + lane;

    float m = -1e30f, l = 0.f, acc = 0.f;

    for (int k0 = 0; k0 < K_SZ; k0 += 8) {
        float kv[8], vv[8];
#pragma unroll
        for (int u = 0; u < 8; ++u) {
            kv[u] = kp[(size_t)(k0 + u) * D_SZ];
            vv[u] = vp[(size_t)(k0 + u) * D_SZ];
        }
        float s[8];
#pragma unroll
        for (int u = 0; u < 8; ++u) s[u] = q * kv[u];
#pragma unroll
        for (int o = 16; o > 0; o >>= 1) {
#pragma unroll
            for (int u = 0; u < 8; ++u)
                s[u] += __shfl_xor_sync(0xffffffffu, s[u], o);
        }
        float mb = s[0];
#pragma unroll
        for (int u = 1; u < 8; ++u) mb = fmaxf(mb, s[u]);
        const float mn   = fmaxf(m, mb);
        const float corr = __expf(m - mn);
        l *= corr;  acc *= corr;
#pragma unroll
        for (int u = 0; u < 8; ++u) {
            const float p = __expf(s[u] - mn);
            l += p;
            acc = fmaf(p, vv[u], acc);
        }
        m = mn;
    }
    const float o_val = acc / l;

    __shared__ float sred[2][8];
    float s = o_val, ss = o_val * o_val;
#pragma unroll
    for (int o = 16; o > 0; o >>= 1) {
        s  += __shfl_xor_sync(0xffffffffu, s,  o);
        ss += __shfl_xor_sync(0xffffffffu, ss, o);
    }
    if (lane == 0) { sred[0][h] = s; sred[1][h] = ss; }
    __syncthreads();
    float ts = 0.f, tss = 0.f;
#pragma unroll
    for (int i = 0; i < 8; ++i) { ts += sred[0][i]; tss += sred[1][i]; }
    const float mu  = ts * (1.f / 256.f);
    const float var = tss * (1.f / 256.f) - mu * mu;
    const float r   = rsqrtf(var + EPS_LN);

    __shared__ float sn[D_SZ];
    sn[tid] = (o_val - mu) * r * n_w[tid] + n_b[tid];
    __syncthreads();

    const float4* w4 = reinterpret_cast<const float4*>(Wp + (size_t)tid * D_SZ);
    const float4* x4 = reinterpret_cast<const float4*>(sn);
    float a = 0.f;
#pragma unroll
    for (int d = 0; d < D_SZ / 4; ++d) {
        float4 w = w4[d];
        float4 x = x4[d];
        a = fmaf(w.x, x.x, a);
        a = fmaf(w.y, x.y, a);
        a = fmaf(w.z, x.z, a);
        a = fmaf(w.w, x.w, a);
    }
    out[b * D_SZ + tid] = a;
}

// ============================================================================
extern "C" void kernel_launch(void* const* d_in, const int* in_sizes, int n_in,
                              void* d_out, int out_size)
{
    const float* x_q  = (const float*)d_in[0];
    const float* x_k  = (const float*)d_in[1];
    const float* x_v  = (const float*)d_in[2];
    const float* Wq   = (const float*)d_in[3];
    const float* Wk   = (const float*)d_in[4];
    const float* Wv   = (const float*)d_in[5];
    const float* Wp   = (const float*)d_in[6];
    const float* qn_w = (const float*)d_in[7];
    const float* qn_b = (const float*)d_in[8];
    const float* kn_w = (const float*)d_in[9];
    const float* kn_b = (const float*)d_in[10];
    const float* n_w  = (const float*)d_in[11];
    const float* n_b  = (const float*)d_in[12];
    float* out = (float*)d_out;

    static int smem_set = 0;
    if (!smem_set) {
        cudaFuncSetAttribute(proj_mma<true>,
                             cudaFuncAttributeMaxDynamicSharedMemorySize, DSM_B);
        cudaFuncSetAttribute(proj_mma<false>,
                             cudaFuncAttributeMaxDynamicSharedMemorySize, DSM_B);
        smem_set = 1;
    }

    const int M_TILES = (B_SZ * K_SZ) / 64;   // 8192

    wsplit_kernel<<<512, 256>>>(Wk, Wv);
    qproj_kernel<<<B_SZ, 256>>>(x_q, Wq, qn_w, qn_b);
    proj_mma<true ><<<M_TILES, 256, DSM_B>>>(x_k, 0, kn_w, kn_b);
    proj_mma<false><<<M_TILES, 256, DSM_B>>>(x_v, 1, nullptr, nullptr);
    attn_kernel<<<B_SZ, 256>>>(Wp, n_w, n_b, out);
}